// round 10
// baseline (speedup 1.0000x reference)
#include <cuda_runtime.h>
#include <cuda_fp16.h>
#include <cstdint>

// Problem constants
#define NB   16        // batch
#define CC   128       // channels
#define HH   112
#define WW   112
#define PLANE (HH*WW)          // 12544 pixels per plane
#define PTS   (98*16*16)       // 25088 sample points per image
#define THREADS 1024
#define FULL_ITERS 24          // 24*1024 = 24576; tail: 512 points

static __device__ __forceinline__ unsigned int h2_bits(__half2 h)
{
    union { __half2 h; unsigned int u; } cvt;
    cvt.h = h;
    return cvt.u;
}

// smem: uint2 per pixel: e[p] = { h2(chA[p],chB[p]), h2(chA[p+1],chB[p+1]) }
// -> 12544 * 8 B = 100,352 B. One LDS.64 per row corner-pair.
// 2 blocks/SM @ 1024 threads -> 64 warps/SM.
__global__ __launch_bounds__(THREADS, 2)
void patches_kernel(const float* __restrict__ fm,
                    const float* __restrict__ grid,
                    float* __restrict__ out)
{
    extern __shared__ uint2 e[];   // PLANE uint2

    const int n  = blockIdx.x >> 6;          // 16 images
    const int c0 = (blockIdx.x & 63) * 2;    // 64 channel pairs

    // ---- Stage: build x-paired half2 entries, conflict-free STS.128 ----
    {
        const float* __restrict__ pA = fm + ((size_t)n * CC + c0) * PLANE;
        const float* __restrict__ pB = pA + PLANE;
        uint4* __restrict__ ed = reinterpret_cast<uint4*>(e);
        for (int i = threadIdx.x; i < PLANE / 2; i += THREADS) {
            const int p0 = 2 * i;
            const float2 a01 = *reinterpret_cast<const float2*>(pA + p0);
            const float2 b01 = *reinterpret_cast<const float2*>(pB + p0);
            float a2 = 0.0f, b2 = 0.0f;
            if (p0 + 2 < PLANE) {           // guarded neighbor (entry never read)
                a2 = pA[p0 + 2];
                b2 = pB[p0 + 2];
            }
            const unsigned int h0 = h2_bits(__floats2half2_rn(a01.x, b01.x));
            const unsigned int h1 = h2_bits(__floats2half2_rn(a01.y, b01.y));
            const unsigned int hv = h2_bits(__floats2half2_rn(a2, b2));
            uint4 v;                         // {e[p0], e[p0+1]}
            v.x = h0; v.y = h1;              // e[p0]   = (h0, h1)
            v.z = h1; v.w = hv;              // e[p0+1] = (h1, h2)
            ed[i] = v;
        }
    }
    __syncthreads();

    // Per-thread pointers: pix = (tid & 255) loop-invariant; p advances by 4.
    const float2* __restrict__ g =
        reinterpret_cast<const float2*>(grid) + (size_t)n * PTS + threadIdx.x;

    // out[n, p, c, hg, wg]  flat = ((n*98 + p)*128 + c)*256 + pix
    float* __restrict__ o = out + (((size_t)n * 98) * CC + c0) * 256
                          + (threadIdx.x >> 8) * (CC * 256)
                          + (threadIdx.x & 255);

    #pragma unroll 4
    for (int i = 0; i <= FULL_ITERS; i++) {
        if (i == FULL_ITERS && threadIdx.x >= 512) break;  // tail: 512 points

        const float2 xy = g[i * THREADS];

        // unnormalize (align_corners=False) + border clamp
        float x = fminf(fmaxf(fmaf(xy.x + 1.0f, 56.0f, -0.5f), 0.0f), 111.0f);
        float y = fminf(fmaxf(fmaf(xy.y + 1.0f, 56.0f, -0.5f), 0.0f), 111.0f);

        // corner clamped to [0,110]; wx in [0,1] (wx=1 reproduces border case)
        const int x0 = min((int)x, WW - 2);
        const int y0 = min((int)y, HH - 2);
        const float wx = x - (float)x0;
        const float wy = y - (float)y0;

        const int b00 = y0 * WW + x0;

        const uint2 row0 = e[b00];        // LDS.64: (q00, q01)
        const uint2 row1 = e[b00 + WW];   // LDS.64: (q10, q11)

        union { unsigned int u; __half2 h; } u00, u01, u10, u11;
        u00.u = row0.x; u01.u = row0.y;
        u10.u = row1.x; u11.u = row1.y;

        // packed fp16 bilinear lerp: 3x HSUB2 + 3x HFMA2
        const __half2 wx2 = __float2half2_rn(wx);
        const __half2 wy2 = __float2half2_rn(wy);
        const __half2 top = __hfma2(wx2, __hsub2(u01.h, u00.h), u00.h);
        const __half2 bot = __hfma2(wx2, __hsub2(u11.h, u10.h), u10.h);
        const __half2 res = __hfma2(wy2, __hsub2(bot, top), top);

        const float2 r = __half22float2(res);

        // each iteration advances p by THREADS/256 = 4 rows of [C,256]
        float* __restrict__ oi = o + i * (4 * CC * 256);
        oi[0]   = r.x;
        oi[256] = r.y;
    }
}

extern "C" void kernel_launch(void* const* d_in, const int* in_sizes, int n_in,
                              void* d_out, int out_size)
{
    const float* fm   = (const float*)d_in[0];   // [16,128,112,112] f32
    const float* grid = (const float*)d_in[1];   // [16,98,16,16,2]  f32
    float* out        = (float*)d_out;           // [16,98,128,16,16] f32

    const int smem = PLANE * sizeof(uint2);      // 100,352 B
    cudaFuncSetAttribute(patches_kernel,
                         cudaFuncAttributeMaxDynamicSharedMemorySize, smem);

    const int blocks = NB * (CC / 2);            // 1024
    patches_kernel<<<blocks, THREADS, smem>>>(fm, grid, out);
}